// round 6
// baseline (speedup 1.0000x reference)
#include <cuda_runtime.h>
#include <math.h>
#include <stdint.h>

// Problem constants (fixed by setup_inputs)
#define BS     8
#define HW     4096       // 64*64
#define VN     204        // hw // STEP
#define STEPV  20
#define PN     400
#define NPAIR  200        // PN/2 packed gt pairs
#define NT     128        // 4 warps
#define NBLK   592        // 148 SMs * 4
#define NWARPS (NBLK * 4)
#define CKV    7          // 64-point chunks per view (6 full + 1 of 16)
#define HITEMS (VN * CKV) // 1428 heavy warp-items per sym batch

// Scratch (no cudaMalloc). Zero at load; last block resets for graph replay.
__device__ double       g_acc[2];     // [0]=loss sum, [1]=value sum
__device__ unsigned int g_count = 0;

// Packed f32x2 FMA (Blackwell FFMA2 — only via PTX)
#define FMA2(d, a, b, c) \
    asm("fma.rn.f32x2 %0, %1, %2, %3;" : "=l"(d) : "l"(a), "l"(b), "l"(c))
#define UNPACK2(lo, hi, v) \
    asm("mov.b64 {%0, %1}, %2;" : "=r"(lo), "=r"(hi) : "l"(v))

__device__ __forceinline__ uint64_t pack2(float lo, float hi) {
    return (uint64_t)__float_as_uint(lo) | ((uint64_t)__float_as_uint(hi) << 32);
}

struct Pose { float R00,R01,R02,R10,R11,R12,R20,R21,R22,t0,t1,t2; };

__device__ __forceinline__ Pose pred_pose(const float* __restrict__ pred_r,
                                          const float* __restrict__ pred_t,
                                          int b, int pix)
{
    const float* prb = pred_r + (size_t)b * 4 * HW;
    float q0 = prb[pix], q1 = prb[HW+pix], q2 = prb[2*HW+pix], q3 = prb[3*HW+pix];
    const float inv = rsqrtf(q0*q0 + q1*q1 + q2*q2 + q3*q3);
    q0 *= inv; q1 *= inv; q2 *= inv; q3 *= inv;
    Pose P;
    P.R00 = 1.0f - 2.0f*(q2*q2 + q3*q3);
    P.R01 = 2.0f*q1*q2 - 2.0f*q0*q3;
    P.R02 = 2.0f*q0*q2 + 2.0f*q1*q3;
    P.R10 = 2.0f*q1*q2 + 2.0f*q3*q0;
    P.R11 = 1.0f - 2.0f*(q1*q1 + q3*q3);
    P.R12 = -2.0f*q0*q1 + 2.0f*q2*q3;
    P.R20 = -2.0f*q0*q2 + 2.0f*q1*q3;
    P.R21 = 2.0f*q0*q1 + 2.0f*q2*q3;
    P.R22 = 1.0f - 2.0f*(q1*q1 + q2*q2);
    const float* ptb = pred_t + (size_t)b * 3 * HW;
    P.t0 = ptb[pix]; P.t1 = ptb[HW+pix]; P.t2 = ptb[2*HW+pix];
    return P;
}

__global__ __launch_bounds__(NT) void loss_kernel(
    const float* __restrict__ pred_r,     // (bs,4,h,w)
    const float* __restrict__ pred_t,     // (bs,3,h,w)
    const float* __restrict__ pred_score, // (bs,h,w)
    const float* __restrict__ gt_r,       // (bs,3,3)
    const float* __restrict__ gt_t,       // (bs,3)
    const int*   __restrict__ cls_ids,    // (bs,)
    const float* __restrict__ model,      // (bs,3,P)
    float* __restrict__ out)
{
    const int tid  = threadIdx.x;
    const int wid  = tid >> 5;
    const int lane = tid & 31;
    const int wgid = blockIdx.x * 4 + wid;

    __shared__ ulonglong2 sA[NPAIR];   // (gx0,gx1),(gy0,gy1)
    __shared__ ulonglong2 sB[NPAIR];   // (gz0,gz1),(gn0,gn1)
    __shared__ double     redd[8];

    // Classify batches (broadcast LDGs)
    unsigned sym_mask = 0u, light_mask = 0u;
    #pragma unroll
    for (int b = 0; b < BS; b++) {
        const int c = cls_ids[b];
        const bool val = (c >= 0 && c <= 29);
        const bool sy  = (c==12 || c==15 || c==18 || c==19 || c==20);
        if (val &&  sy) sym_mask   |= (1u << b);
        if (val && !sy) light_mask |= (1u << b);
    }
    const int ns = __popc(sym_mask);
    const int nl = __popc(light_mask);

    double accL = 0.0, accV = 0.0;   // per-warp (uniform across lanes)
    const float invPN = 1.0f / (float)PN;

    // ===== Heavy phase: one barrier per sym batch; items are per-WARP ======
    for (int bi = 0; bi < ns; bi++) {
        const int b = __fns(sym_mask, 0, bi + 1);
        const float* mb = model + (size_t)b * 3 * PN;

        if (bi > 0) __syncthreads();   // all warps done reading previous stage
        {   // stage packed gt pairs (pair j = points 2j,2j+1)
            const float r00 = gt_r[b*9+0], r01 = gt_r[b*9+1], r02 = gt_r[b*9+2];
            const float r10 = gt_r[b*9+3], r11 = gt_r[b*9+4], r12 = gt_r[b*9+5];
            const float r20 = gt_r[b*9+6], r21 = gt_r[b*9+7], r22 = gt_r[b*9+8];
            const float t0g = gt_t[b*3+0], t1g = gt_t[b*3+1], t2g = gt_t[b*3+2];
            for (int j = tid; j < NPAIR; j += NT) {
                const float x0 = mb[2*j],   y0 = mb[PN+2*j],   z0 = mb[2*PN+2*j];
                const float x1 = mb[2*j+1], y1 = mb[PN+2*j+1], z1 = mb[2*PN+2*j+1];
                const float gx0 = r00*x0 + r01*y0 + r02*z0 + t0g;
                const float gy0 = r10*x0 + r11*y0 + r12*z0 + t1g;
                const float gz0 = r20*x0 + r21*y0 + r22*z0 + t2g;
                const float gx1 = r00*x1 + r01*y1 + r02*z1 + t0g;
                const float gy1 = r10*x1 + r11*y1 + r12*z1 + t1g;
                const float gz1 = r20*x1 + r21*y1 + r22*z1 + t2g;
                sA[j] = make_ulonglong2(pack2(gx0,gx1), pack2(gy0,gy1));
                sB[j] = make_ulonglong2(pack2(gz0,gz1),
                                        pack2(gx0*gx0+gy0*gy0+gz0*gz0,
                                              gx1*gx1+gy1*gy1+gz1*gz1));
            }
        }
        __syncthreads();

        // Per-warp items: (view v, 64-point chunk ck)
        for (int it = wgid; it < HITEMS; it += NWARPS) {
            const int v  = it / CKV;
            const int ck = it - v * CKV;
            const int pix = v * STEPV;
            const Pose P = pred_pose(pred_r, pred_t, b, pix);
            const float sc = pred_score[(size_t)b * HW + pix];

            const int p0 = ck * 64 + lane;
            const int p1 = p0 + 32;
            const bool act0 = (p0 < PN);
            const bool act1 = (p1 < PN);
            const int pp0 = act0 ? p0 : (PN - 1);
            const int pp1 = act1 ? p1 : (PN - 1);

            const float x0 = mb[pp0], y0 = mb[PN+pp0], z0 = mb[2*PN+pp0];
            const float x1 = mb[pp1], y1 = mb[PN+pp1], z1 = mb[2*PN+pp1];
            const float px0 = P.R00*x0 + P.R01*y0 + P.R02*z0 + P.t0;
            const float py0 = P.R10*x0 + P.R11*y0 + P.R12*z0 + P.t1;
            const float pz0 = P.R20*x0 + P.R21*y0 + P.R22*z0 + P.t2;
            const float px1 = P.R00*x1 + P.R01*y1 + P.R02*z1 + P.t0;
            const float py1 = P.R10*x1 + P.R11*y1 + P.R12*z1 + P.t1;
            const float pz1 = P.R20*x1 + P.R21*y1 + P.R22*z1 + P.t2;
            const float pn0 = px0*px0 + py0*py0 + pz0*pz0;
            const float pn1 = px1*px1 + py1*py1 + pz1*pz1;
            const uint64_t ax0 = pack2(-2.0f*px0, -2.0f*px0);
            const uint64_t ay0 = pack2(-2.0f*py0, -2.0f*py0);
            const uint64_t az0 = pack2(-2.0f*pz0, -2.0f*pz0);
            const uint64_t ax1 = pack2(-2.0f*px1, -2.0f*px1);
            const uint64_t ay1 = pack2(-2.0f*py1, -2.0f*py1);
            const uint64_t az1 = pack2(-2.0f*pz1, -2.0f*pz1);

            float mlo0 = 3.4e38f, mhi0 = 3.4e38f;
            float mlo1 = 3.4e38f, mhi1 = 3.4e38f;
            #pragma unroll 4
            for (int j = 0; j < NPAIR; j++) {
                const ulonglong2 A = sA[j];   // LDS.128 broadcast
                const ulonglong2 B = sB[j];
                uint64_t t0, t1;
                FMA2(t0, az0, B.x, B.y);
                FMA2(t0, ay0, A.y, t0);
                FMA2(t0, ax0, A.x, t0);
                FMA2(t1, az1, B.x, B.y);
                FMA2(t1, ay1, A.y, t1);
                FMA2(t1, ax1, A.x, t1);
                uint32_t lo, hi;
                UNPACK2(lo, hi, t0);
                mlo0 = fminf(mlo0, __uint_as_float(lo));
                mhi0 = fminf(mhi0, __uint_as_float(hi));
                UNPACK2(lo, hi, t1);
                mlo1 = fminf(mlo1, __uint_as_float(lo));
                mhi1 = fminf(mhi1, __uint_as_float(hi));
            }
            float s = 0.0f;
            if (act0) s += sqrtf(fmaxf(pn0 + fminf(mlo0, mhi0), 0.0f));
            if (act1) s += sqrtf(fmaxf(pn1 + fminf(mlo1, mhi1), 0.0f));

            // Butterfly: all lanes get the chunk total
            #pragma unroll
            for (int off = 16; off > 0; off >>= 1)
                s += __shfl_xor_sync(0xFFFFFFFFu, s, off);

            const float part = s * invPN;
            float lc = part * sc;
            if (ck == 0) lc += -0.01f * logf(sc);  // log term once per view
            accL += (double)lc;
            accV += (double)part;
        }
    }

    // ===== Light phase: ADD, per-warp items, no barriers, no smem ==========
    const int L = VN * nl;
    for (int l = wgid; l < L; l += NWARPS) {
        const int b_idx = l / VN;
        const int v     = l - b_idx * VN;
        const int b     = __fns(light_mask, 0, b_idx + 1);

        const float r00 = gt_r[b*9+0], r01 = gt_r[b*9+1], r02 = gt_r[b*9+2];
        const float r10 = gt_r[b*9+3], r11 = gt_r[b*9+4], r12 = gt_r[b*9+5];
        const float r20 = gt_r[b*9+6], r21 = gt_r[b*9+7], r22 = gt_r[b*9+8];
        const float t0g = gt_t[b*3+0], t1g = gt_t[b*3+1], t2g = gt_t[b*3+2];
        const float* mb = model + (size_t)b * 3 * PN;

        const int pix = v * STEPV;
        const Pose P = pred_pose(pred_r, pred_t, b, pix);
        const float sc = pred_score[(size_t)b * HW + pix];

        float s = 0.0f;
        for (int p = lane; p < PN; p += 32) {
            const float x = mb[p], y = mb[PN+p], z = mb[2*PN+p];
            const float dx = P.R00*x + P.R01*y + P.R02*z + P.t0 - (r00*x + r01*y + r02*z + t0g);
            const float dy = P.R10*x + P.R11*y + P.R12*z + P.t1 - (r10*x + r11*y + r12*z + t1g);
            const float dz = P.R20*x + P.R21*y + P.R22*z + P.t2 - (r20*x + r21*y + r22*z + t2g);
            s += sqrtf(dx*dx + dy*dy + dz*dz);
        }
        #pragma unroll
        for (int off = 16; off > 0; off >>= 1)
            s += __shfl_xor_sync(0xFFFFFFFFu, s, off);

        const float add_ij = s * invPN;
        accL += (double)(add_ij * sc - 0.01f * logf(sc));
        accV += (double)add_ij;
    }

    // ===== Combine: per-warp -> block -> 2 atomics ==========================
    if (lane == 0) { redd[wid*2] = accL; redd[wid*2+1] = accV; }
    __syncthreads();

    if (tid == 0) {
        double Lacc = 0.0, Vacc = 0.0;
        #pragma unroll
        for (int w = 0; w < 4; w++) { Lacc += redd[w*2]; Vacc += redd[w*2+1]; }
        const double scale = 1.0 / ((double)VN * (double)BS);
        atomicAdd(&g_acc[0], Lacc * scale);
        atomicAdd(&g_acc[1], Vacc * scale);
        __threadfence();
        const unsigned int old = atomicAdd(&g_count, 1u);
        if (old == (unsigned int)(NBLK - 1)) {
            __threadfence();
            const double gl = *(volatile double*)&g_acc[0];
            const double gv = *(volatile double*)&g_acc[1];
            float glf = (float)gl;
            const float gvf = (float)gv;
            if (isinf(glf) || isnan(glf)) glf = 0.0f;
            out[0] = glf + 0.0f * gvf;   // faithful to reference
            g_acc[0] = 0.0;
            g_acc[1] = 0.0;
            g_count  = 0u;
        }
    }
}

extern "C" void kernel_launch(void* const* d_in, const int* in_sizes, int n_in,
                              void* d_out, int out_size) {
    const float* pred_r     = (const float*)d_in[0];
    const float* pred_t     = (const float*)d_in[1];
    const float* pred_score = (const float*)d_in[2];
    const float* gt_r       = (const float*)d_in[3];
    const float* gt_t       = (const float*)d_in[4];
    const int*   cls_ids    = (const int*)  d_in[5];
    const float* model_xyz  = (const float*)d_in[6];
    float* out = (float*)d_out;

    loss_kernel<<<NBLK, NT>>>(pred_r, pred_t, pred_score, gt_r, gt_t,
                              cls_ids, model_xyz, out);
}